// round 3
// baseline (speedup 1.0000x reference)
#include <cuda_runtime.h>
#include <cstdint>

// ---------------- problem constants ----------------
#define MTOT 4096
#define NTOT 2048
#define KTOT 2048
#define BM   128
#define BN   128
#define BK   32
#define STAGES 3
#define KSTEPS (KTOT / BK)          // 64
#define THREADS 256

// padded smem row: 32 floats data + 4 pad -> 36 floats (144B)
#define ROWF 36
#define ASTG (BM * ROWF * 4)        // 18432 bytes per stage (A or B)

// ---------------- smem layout (bytes) ----------------
#define SM_BIAS 0
#define SM_GNW  512
#define SM_GNB  1024
#define SM_A    2048
#define SM_B    (SM_A + STAGES * ASTG)            // 57344
#define SMEM_TOTAL (SM_B + STAGES * ASTG)         // 112640

// ---------------- PTX helpers ----------------
__device__ __forceinline__ uint32_t smem_u32(const void* p) {
    uint32_t a;
    asm("{ .reg .u64 t; cvta.to.shared.u64 t, %1; cvt.u32.u64 %0, t; }"
        : "=r"(a) : "l"(p));
    return a;
}

#define CP_ASYNC16(s, g) \
    asm volatile("cp.async.cg.shared.global [%0], [%1], 16;" :: "r"(s), "l"(g) : "memory")
#define CP_COMMIT() asm volatile("cp.async.commit_group;" ::: "memory")
#define CP_WAIT(n)  asm volatile("cp.async.wait_group %0;" :: "n"(n) : "memory")

__device__ __forceinline__ uint32_t f2tf32(float f) {
    uint32_t r;
    asm("cvt.rna.tf32.f32 %0, %1;" : "=r"(r) : "f"(f));
    return r;
}

__device__ __forceinline__ void mma_tf32(float* c, const uint32_t* a, const uint32_t* b) {
    asm volatile(
        "mma.sync.aligned.m16n8k8.row.col.f32.tf32.tf32.f32 "
        "{%0,%1,%2,%3}, {%4,%5,%6,%7}, {%8,%9}, {%0,%1,%2,%3};"
        : "+f"(c[0]), "+f"(c[1]), "+f"(c[2]), "+f"(c[3])
        : "r"(a[0]), "r"(a[1]), "r"(a[2]), "r"(a[3]),
          "r"(b[0]), "r"(b[1]));
}

// ---------------- stage load: A[128][32] + B[128][32] f32, padded rows ----------------
__device__ __forceinline__ void load_stage(const float* __restrict__ ga0,
                                           const float* __restrict__ gb0,
                                           int ks, int s, uint32_t sb, int tid) {
    uint32_t sA = sb + SM_A + s * ASTG;
    uint32_t sB = sb + SM_B + s * ASTG;
    const float* ga = ga0 + ks * BK;
    const float* gb = gb0 + ks * BK;
#pragma unroll
    for (int i = 0; i < 4; i++) {              // 1024 16B-chunks / 256 thr = 4
        int q = tid + i * THREADS;
        int r = q >> 3, c = q & 7;
        CP_ASYNC16(sA + (r * ROWF + c * 4) * 4, ga + (size_t)r * KTOT + c * 4);
    }
#pragma unroll
    for (int i = 0; i < 4; i++) {
        int q = tid + i * THREADS;
        int r = q >> 3, c = q & 7;
        CP_ASYNC16(sB + (r * ROWF + c * 4) * 4, gb + (size_t)r * KTOT + c * 4);
    }
}

// ---------------- kernel ----------------
__global__ void __launch_bounds__(THREADS, 2)
fused_linear_gn_ht_kernel(const float* __restrict__ x,
                          const float* __restrict__ w,
                          const float* __restrict__ bias,
                          const float* __restrict__ gnw,
                          const float* __restrict__ gnb,
                          float* __restrict__ out) {
    extern __shared__ char smem[];
    uint32_t sb = smem_u32(smem);
    int tid = threadIdx.x;
    int wid = tid >> 5, lid = tid & 31;
    int wm = wid >> 1, wn = wid & 1;           // warp grid 4 (M) x 2 (N)
    int gid = lid >> 2, tid4 = lid & 3;
    int bn = blockIdx.x, bm = blockIdx.y;

    float* bias_s = (float*)(smem + SM_BIAS);
    float* gnw_s  = (float*)(smem + SM_GNW);
    float* gnb_s  = (float*)(smem + SM_GNB);
    if (tid < BN) {
        bias_s[tid] = bias[bn * BN + tid];
        gnw_s[tid]  = gnw[bn * BN + tid];
        gnb_s[tid]  = gnb[bn * BN + tid];
    }

    const float* ga0 = x + (size_t)bm * BM * KTOT;
    const float* gb0 = w + (size_t)bn * BN * KTOT;

    // prologue: stages 0, 1
#pragma unroll
    for (int p = 0; p < STAGES - 1; p++) {
        load_stage(ga0, gb0, p, p, sb, tid);
        CP_COMMIT();
    }

    float acc[2][8][4];
#pragma unroll
    for (int mi = 0; mi < 2; mi++)
#pragma unroll
        for (int ni = 0; ni < 8; ni++)
#pragma unroll
            for (int j = 0; j < 4; j++) acc[mi][ni][j] = 0.f;

    int s = 0;                 // stage being computed
    int ps = STAGES - 1;       // stage being prefetched
    for (int k = 0; k < KSTEPS; k++) {
        CP_WAIT(STAGES - 2);
        __syncthreads();

        int lk = k + STAGES - 1;
        if (lk < KSTEPS) {
            load_stage(ga0, gb0, lk, ps, sb, tid);
        }
        CP_COMMIT();

        const float* As = (const float*)(smem + SM_A + s * ASTG);
        const float* Bs = (const float*)(smem + SM_B + s * ASTG);

#pragma unroll
        for (int kk = 0; kk < 4; kk++) {
            int k0 = kk * 8;
            uint32_t af[2][4], bf[8][2];
#pragma unroll
            for (int mi = 0; mi < 2; mi++) {
                int r = wm * 32 + mi * 16 + gid;
                af[mi][0] = f2tf32(As[r * ROWF + k0 + tid4]);
                af[mi][1] = f2tf32(As[(r + 8) * ROWF + k0 + tid4]);
                af[mi][2] = f2tf32(As[r * ROWF + k0 + tid4 + 4]);
                af[mi][3] = f2tf32(As[(r + 8) * ROWF + k0 + tid4 + 4]);
            }
#pragma unroll
            for (int ni = 0; ni < 8; ni++) {
                int n = wn * 64 + ni * 8 + gid;
                bf[ni][0] = f2tf32(Bs[n * ROWF + k0 + tid4]);
                bf[ni][1] = f2tf32(Bs[n * ROWF + k0 + tid4 + 4]);
            }
#pragma unroll
            for (int mi = 0; mi < 2; mi++)
#pragma unroll
                for (int ni = 0; ni < 8; ni++)
                    mma_tf32(acc[mi][ni], af[mi], bf[ni]);
        }

        s = (s + 1 == STAGES) ? 0 : s + 1;
        ps = (ps + 1 == STAGES) ? 0 : ps + 1;
    }

    // ---------------- fused epilogue: bias + GroupNorm(64) + hardtanh ----------------
    // warp tile N=64 == exactly one group; rows handled per (mi, half).
    int gcol = wn * 64;                            // group-local col base in tile
    size_t gout = (size_t)bn * BN + gcol;          // global col base

#pragma unroll
    for (int mi = 0; mi < 2; mi++) {
#pragma unroll
        for (int half = 0; half < 2; half++) {
            int row_l = wm * 32 + mi * 16 + half * 8 + gid;
            float sum = 0.f, ssq = 0.f;
            float v[8][2];
#pragma unroll
            for (int ni = 0; ni < 8; ni++) {
                int c = ni * 8 + 2 * tid4;
                float v0 = acc[mi][ni][half * 2 + 0] + bias_s[gcol + c + 0];
                float v1 = acc[mi][ni][half * 2 + 1] + bias_s[gcol + c + 1];
                v[ni][0] = v0; v[ni][1] = v1;
                sum += v0 + v1;
                ssq += v0 * v0 + v1 * v1;
            }
            // reduce across the 4 lanes (tid4) sharing this row
            sum += __shfl_xor_sync(0xffffffffu, sum, 1);
            ssq += __shfl_xor_sync(0xffffffffu, ssq, 1);
            sum += __shfl_xor_sync(0xffffffffu, sum, 2);
            ssq += __shfl_xor_sync(0xffffffffu, ssq, 2);

            float mean = sum * (1.f / 64.f);
            float var  = ssq * (1.f / 64.f) - mean * mean;
            float inv  = rsqrtf(var + 1e-5f);

            size_t orow = (size_t)(bm * BM + row_l) * NTOT + gout;
#pragma unroll
            for (int ni = 0; ni < 8; ni++) {
                int c = ni * 8 + 2 * tid4;
                float2 o;
                o.x = fminf(fmaxf((v[ni][0] - mean) * inv * gnw_s[gcol + c + 0]
                                  + gnb_s[gcol + c + 0], -1.f), 1.f);
                o.y = fminf(fmaxf((v[ni][1] - mean) * inv * gnw_s[gcol + c + 1]
                                  + gnb_s[gcol + c + 1], -1.f), 1.f);
                *(float2*)(out + orow + c) = o;
            }
        }
    }
}

// ---------------- launch ----------------
extern "C" void kernel_launch(void* const* d_in, const int* in_sizes, int n_in,
                              void* d_out, int out_size) {
    const float* x    = (const float*)d_in[0];
    const float* w    = (const float*)d_in[1];
    const float* bias = (const float*)d_in[2];
    const float* gnw  = (const float*)d_in[3];
    const float* gnb  = (const float*)d_in[4];
    float* out = (float*)d_out;

    static bool attr_done = false;
    if (!attr_done) {
        cudaFuncSetAttribute(fused_linear_gn_ht_kernel,
                             cudaFuncAttributeMaxDynamicSharedMemorySize, SMEM_TOTAL);
        attr_done = true;
    }

    dim3 grid(NTOT / BN, MTOT / BM);   // (16, 32) = 512 CTAs
    fused_linear_gn_ht_kernel<<<grid, THREADS, SMEM_TOTAL>>>(x, w, bias, gnw, gnb, out);
}

// round 4
// speedup vs baseline: 1.1926x; 1.1926x over previous
#include <cuda_runtime.h>
#include <cstdint>

// ---------------- problem constants ----------------
#define MTOT 4096
#define NTOT 2048
#define KTOT 2048
#define BM   128
#define BN   128
#define BK   32
#define STAGES 3
#define KSTEPS (KTOT / BK)          // 64
#define THREADS 256

// smem stage row: 32 floats (128B), XOR-swizzled chunks, no padding
#define ASTG (BM * 128)             // 16384 bytes per stage (A or B)

// ---------------- smem layout (bytes) ----------------
#define SM_BIAS 0
#define SM_GNW  512
#define SM_GNB  1024
#define SM_A    2048
#define SM_B    (SM_A + STAGES * ASTG)            // 51200
#define SMEM_TOTAL (SM_B + STAGES * ASTG)         // 100352 (98KB) -> 2 CTA/SM

// ---------------- tf32-rounded, column-permuted scratch ----------------
__device__ float g_xs[(size_t)MTOT * KTOT];   // 32 MB
__device__ float g_ws[(size_t)NTOT * KTOT];   // 16 MB

// ---------------- PTX helpers ----------------
__device__ __forceinline__ uint32_t smem_u32(const void* p) {
    uint32_t a;
    asm("{ .reg .u64 t; cvta.to.shared.u64 t, %1; cvt.u32.u64 %0, t; }"
        : "=r"(a) : "l"(p));
    return a;
}

#define CP_ASYNC16(s, g) \
    asm volatile("cp.async.cg.shared.global [%0], [%1], 16;" :: "r"(s), "l"(g) : "memory")
#define CP_COMMIT() asm volatile("cp.async.commit_group;" ::: "memory")
#define CP_WAIT(n)  asm volatile("cp.async.wait_group %0;" :: "n"(n) : "memory")

__device__ __forceinline__ float f2tf32f(float f) {
    uint32_t r;
    asm("cvt.rna.tf32.f32 %0, %1;" : "=r"(r) : "f"(f));
    return __uint_as_float(r);
}

__device__ __forceinline__ void mma_tf32(float* c, const uint32_t* a, const uint32_t* b) {
    asm volatile(
        "mma.sync.aligned.m16n8k8.row.col.f32.tf32.tf32.f32 "
        "{%0,%1,%2,%3}, {%4,%5,%6,%7}, {%8,%9}, {%0,%1,%2,%3};"
        : "+f"(c[0]), "+f"(c[1]), "+f"(c[2]), "+f"(c[3])
        : "r"(a[0]), "r"(a[1]), "r"(a[2]), "r"(a[3]),
          "r"(b[0]), "r"(b[1]));
}

// ---------------- prepass: round to tf32 + permute each 8-col block ----------------
// dst block layout: [s0,s4,s1,s5,s2,s6,s3,s7] so fragment pairs are float2-contiguous
__global__ void __launch_bounds__(256)
prepass_kernel(const float* __restrict__ src, float* __restrict__ dst, int nblk) {
    int i = blockIdx.x * 256 + threadIdx.x;
    if (i >= nblk) return;
    const float4* s = (const float4*)src + (size_t)i * 2;
    float4 a = s[0], b = s[1];
    float4 o0, o1;
    o0.x = f2tf32f(a.x); o0.y = f2tf32f(b.x); o0.z = f2tf32f(a.y); o0.w = f2tf32f(b.y);
    o1.x = f2tf32f(a.z); o1.y = f2tf32f(b.z); o1.z = f2tf32f(a.w); o1.w = f2tf32f(b.w);
    float4* d = (float4*)dst + (size_t)i * 2;
    d[0] = o0; d[1] = o1;
}

// ---------------- stage load: A[128][32] + B[128][32], swizzled chunks ----------------
// chunk c (16B) of row r lands at physical chunk c ^ ((r&3)<<1)
__device__ __forceinline__ void load_stage(const float* __restrict__ ga0,
                                           const float* __restrict__ gb0,
                                           int ks, int s, uint32_t sb, int tid) {
    uint32_t sA = sb + SM_A + s * ASTG;
    uint32_t sB = sb + SM_B + s * ASTG;
    const float* ga = ga0 + ks * BK;
    const float* gb = gb0 + ks * BK;
#pragma unroll
    for (int i = 0; i < 4; i++) {              // 1024 16B-chunks / 256 thr = 4
        int q = tid + i * THREADS;
        int r = q >> 3, c = q & 7;
        int cp = c ^ ((r & 3) << 1);
        CP_ASYNC16(sA + r * 128 + cp * 16, ga + (size_t)r * KTOT + c * 4);
    }
#pragma unroll
    for (int i = 0; i < 4; i++) {
        int q = tid + i * THREADS;
        int r = q >> 3, c = q & 7;
        int cp = c ^ ((r & 3) << 1);
        CP_ASYNC16(sB + r * 128 + cp * 16, gb + (size_t)r * KTOT + c * 4);
    }
}

// ---------------- kernel ----------------
__global__ void __launch_bounds__(THREADS, 2)
fused_linear_gn_ht_kernel(const float* __restrict__ xs,
                          const float* __restrict__ ws,
                          const float* __restrict__ bias,
                          const float* __restrict__ gnw,
                          const float* __restrict__ gnb,
                          float* __restrict__ out) {
    extern __shared__ char smem[];
    uint32_t sb = smem_u32(smem);
    int tid = threadIdx.x;
    int wid = tid >> 5, lid = tid & 31;
    int wm = wid >> 1, wn = wid & 1;           // warp grid 4 (M) x 2 (N)
    int gid = lid >> 2, tid4 = lid & 3;
    int bn = blockIdx.x, bm = blockIdx.y;

    float* bias_s = (float*)(smem + SM_BIAS);
    float* gnw_s  = (float*)(smem + SM_GNW);
    float* gnb_s  = (float*)(smem + SM_GNB);
    if (tid < BN) {
        bias_s[tid] = bias[bn * BN + tid];
        gnw_s[tid]  = gnw[bn * BN + tid];
        gnb_s[tid]  = gnb[bn * BN + tid];
    }

    const float* ga0 = xs + (size_t)bm * BM * KTOT;
    const float* gb0 = ws + (size_t)bn * BN * KTOT;

#pragma unroll
    for (int p = 0; p < STAGES - 1; p++) {
        load_stage(ga0, gb0, p, p, sb, tid);
        CP_COMMIT();
    }

    float acc[2][8][4];
#pragma unroll
    for (int mi = 0; mi < 2; mi++)
#pragma unroll
        for (int ni = 0; ni < 8; ni++)
#pragma unroll
            for (int j = 0; j < 4; j++) acc[mi][ni][j] = 0.f;

    // per-thread invariant column offset pieces (floats):
    // logical chunk = kk*2 + (tid4>>1); phys = chunk ^ sw; + (tid4&1)*2 floats
    int sw   = (gid & 3) << 1;
    int t4h  = tid4 >> 1;
    int t4l2 = (tid4 & 1) << 1;

    int rowA0 = wm * 32 + gid;                 // mi=0 row (mi=1 adds 16)
    int rowB0 = wn * 64 + gid;

    int s = 0, ps = STAGES - 1;
    for (int k = 0; k < KSTEPS; k++) {
        CP_WAIT(STAGES - 2);
        __syncthreads();

        int lk = k + STAGES - 1;
        if (lk < KSTEPS) {
            load_stage(ga0, gb0, lk, ps, sb, tid);
        }
        CP_COMMIT();

        const float* As = (const float*)(smem + SM_A + s * ASTG);
        const float* Bs = (const float*)(smem + SM_B + s * ASTG);

#pragma unroll
        for (int kk = 0; kk < 4; kk++) {
            int colOff = (((kk * 2 + t4h) ^ sw) << 2) + t4l2;   // floats within row
            uint32_t af[2][4], bf[8][2];
#pragma unroll
            for (int mi = 0; mi < 2; mi++) {
                int r = rowA0 + mi * 16;
                float2 v0 = *(const float2*)(As + r * 32 + colOff);
                float2 v1 = *(const float2*)(As + (r + 8) * 32 + colOff);
                af[mi][0] = __float_as_uint(v0.x);
                af[mi][2] = __float_as_uint(v0.y);
                af[mi][1] = __float_as_uint(v1.x);
                af[mi][3] = __float_as_uint(v1.y);
            }
#pragma unroll
            for (int ni = 0; ni < 8; ni++) {
                float2 v = *(const float2*)(Bs + (rowB0 + ni * 8) * 32 + colOff);
                bf[ni][0] = __float_as_uint(v.x);
                bf[ni][1] = __float_as_uint(v.y);
            }
#pragma unroll
            for (int mi = 0; mi < 2; mi++)
#pragma unroll
                for (int ni = 0; ni < 8; ni++)
                    mma_tf32(acc[mi][ni], af[mi], bf[ni]);
        }

        s = (s + 1 == STAGES) ? 0 : s + 1;
        ps = (ps + 1 == STAGES) ? 0 : ps + 1;
    }

    // ---------------- fused epilogue: bias + GroupNorm(64) + hardtanh ----------------
    int gcol = wn * 64;
    size_t gout = (size_t)bn * BN + gcol;

#pragma unroll
    for (int mi = 0; mi < 2; mi++) {
#pragma unroll
        for (int half = 0; half < 2; half++) {
            int row_l = wm * 32 + mi * 16 + half * 8 + gid;
            float sum = 0.f, ssq = 0.f;
            float v[8][2];
#pragma unroll
            for (int ni = 0; ni < 8; ni++) {
                int c = ni * 8 + 2 * tid4;
                float v0 = acc[mi][ni][half * 2 + 0] + bias_s[gcol + c + 0];
                float v1 = acc[mi][ni][half * 2 + 1] + bias_s[gcol + c + 1];
                v[ni][0] = v0; v[ni][1] = v1;
                sum += v0 + v1;
                ssq += v0 * v0 + v1 * v1;
            }
            sum += __shfl_xor_sync(0xffffffffu, sum, 1);
            ssq += __shfl_xor_sync(0xffffffffu, ssq, 1);
            sum += __shfl_xor_sync(0xffffffffu, sum, 2);
            ssq += __shfl_xor_sync(0xffffffffu, ssq, 2);

            float mean = sum * (1.f / 64.f);
            float var  = ssq * (1.f / 64.f) - mean * mean;
            float inv  = rsqrtf(var + 1e-5f);

            size_t orow = (size_t)(bm * BM + row_l) * NTOT + gout;
#pragma unroll
            for (int ni = 0; ni < 8; ni++) {
                int c = ni * 8 + 2 * tid4;
                float2 o;
                o.x = fminf(fmaxf((v[ni][0] - mean) * inv * gnw_s[gcol + c + 0]
                                  + gnb_s[gcol + c + 0], -1.f), 1.f);
                o.y = fminf(fmaxf((v[ni][1] - mean) * inv * gnw_s[gcol + c + 1]
                                  + gnb_s[gcol + c + 1], -1.f), 1.f);
                *(float2*)(out + orow + c) = o;
            }
        }
    }
}

// ---------------- launch ----------------
extern "C" void kernel_launch(void* const* d_in, const int* in_sizes, int n_in,
                              void* d_out, int out_size) {
    const float* x    = (const float*)d_in[0];
    const float* w    = (const float*)d_in[1];
    const float* bias = (const float*)d_in[2];
    const float* gnw  = (const float*)d_in[3];
    const float* gnb  = (const float*)d_in[4];
    float* out = (float*)d_out;

    static bool attr_done = false;
    if (!attr_done) {
        cudaFuncSetAttribute(fused_linear_gn_ht_kernel,
                             cudaFuncAttributeMaxDynamicSharedMemorySize, SMEM_TOTAL);
        attr_done = true;
    }

    float* xs; float* ws;
    cudaGetSymbolAddress((void**)&xs, g_xs);
    cudaGetSymbolAddress((void**)&ws, g_ws);

    int nblk_x = (MTOT * KTOT) / 8;   // 1,048,576
    int nblk_w = (NTOT * KTOT) / 8;   //   524,288
    prepass_kernel<<<(nblk_x + 255) / 256, 256>>>(x, xs, nblk_x);
    prepass_kernel<<<(nblk_w + 255) / 256, 256>>>(w, ws, nblk_w);

    dim3 grid(NTOT / BN, MTOT / BM);   // (16, 32) = 512 CTAs
    fused_linear_gn_ht_kernel<<<grid, THREADS, SMEM_TOTAL>>>(xs, ws, bias, gnw, gnb, out);
}

// round 5
// speedup vs baseline: 1.8319x; 1.5360x over previous
#include <cuda_runtime.h>
#include <cuda_fp16.h>
#include <cstdint>

// ---------------- problem constants ----------------
#define MTOT 4096
#define NTOT 2048
#define KTOT 2048
#define BM   128
#define BN   128
#define BK   32
#define STAGES 4
#define KSTEPS (KTOT / BK)          // 64
#define THREADS 256

// fp16 smem stage row: 32 halves = 64B, permuted so each thread's fragment is LDS.128
#define ROWB 64
#define ASTG (BM * ROWB)            // 8192 bytes per stage (A or B)

// ---------------- smem layout (bytes) ----------------
#define SM_BIAS 0
#define SM_GNW  512
#define SM_GNB  1024
#define SM_A    2048
#define SM_B    (SM_A + STAGES * ASTG)            // 34816
#define SMEM_TOTAL (SM_B + STAGES * ASTG)         // 67584 (66KB) -> 2 CTA/SM

// ---------------- fp16, fragment-permuted scratch ----------------
__device__ __half g_xsh[(size_t)MTOT * KTOT];   // 16 MB
__device__ __half g_wsh[(size_t)NTOT * KTOT];   //  8 MB

// ---------------- PTX helpers ----------------
__device__ __forceinline__ uint32_t smem_u32(const void* p) {
    uint32_t a;
    asm("{ .reg .u64 t; cvta.to.shared.u64 t, %1; cvt.u32.u64 %0, t; }"
        : "=r"(a) : "l"(p));
    return a;
}

#define CP_ASYNC16(s, g) \
    asm volatile("cp.async.cg.shared.global [%0], [%1], 16;" :: "r"(s), "l"(g) : "memory")
#define CP_COMMIT() asm volatile("cp.async.commit_group;" ::: "memory")
#define CP_WAIT(n)  asm volatile("cp.async.wait_group %0;" :: "n"(n) : "memory")

#define LDS128(r0, r1, r2, r3, addr) \
    asm volatile("ld.shared.v4.u32 {%0, %1, %2, %3}, [%4];" \
                 : "=r"(r0), "=r"(r1), "=r"(r2), "=r"(r3) : "r"(addr))

__device__ __forceinline__ void mma_f16(float* c, uint32_t a0, uint32_t a1,
                                        uint32_t a2, uint32_t a3,
                                        uint32_t b0, uint32_t b1) {
    asm volatile(
        "mma.sync.aligned.m16n8k16.row.col.f32.f16.f16.f32 "
        "{%0,%1,%2,%3}, {%4,%5,%6,%7}, {%8,%9}, {%0,%1,%2,%3};"
        : "+f"(c[0]), "+f"(c[1]), "+f"(c[2]), "+f"(c[3])
        : "r"(a0), "r"(a1), "r"(a2), "r"(a3), "r"(b0), "r"(b1));
}

// ---------------- prepass: fp32 -> fp16 + fragment permutation ----------------
// Per row, per 32-col K-step block, layout (halves, 64B):
//   t4 chunk (16B) = [blk0: c(2t4), c(2t4+1), c(2t4+8), c(2t4+9) | blk1: +16 cols same]
// so thread tid4 of a warp loads its m16n8k16 A/B fragment halves for BOTH k16
// sub-blocks with a single LDS.128.
__global__ void __launch_bounds__(256)
prepass_kernel(const float* __restrict__ x, const float* __restrict__ w, int nunit) {
    int u = blockIdx.x * 256 + threadIdx.x;
    if (u >= nunit) return;
    int row = u >> 6;                  // 64 units of 32 cols per 2048-col row
    int uc  = u & 63;
    const float* src;
    __half* dst;
    if (row < MTOT) {
        src = x + (size_t)row * KTOT + uc * 32;
        dst = g_xsh + (size_t)row * KTOT + uc * 32;
    } else {
        src = w + (size_t)(row - MTOT) * KTOT + uc * 32;
        dst = g_wsh + (size_t)(row - MTOT) * KTOT + uc * 32;
    }
    float v[32];
#pragma unroll
    for (int i = 0; i < 8; i++) {
        float4 f = ((const float4*)src)[i];
        v[i * 4 + 0] = f.x; v[i * 4 + 1] = f.y; v[i * 4 + 2] = f.z; v[i * 4 + 3] = f.w;
    }
    __half h[32];
#pragma unroll
    for (int t4 = 0; t4 < 4; t4++) {
#pragma unroll
        for (int blk = 0; blk < 2; blk++) {
            int o = t4 * 8 + blk * 4;
            int c = blk * 16 + 2 * t4;
            h[o + 0] = __float2half_rn(v[c + 0]);
            h[o + 1] = __float2half_rn(v[c + 1]);
            h[o + 2] = __float2half_rn(v[c + 8]);
            h[o + 3] = __float2half_rn(v[c + 9]);
        }
    }
#pragma unroll
    for (int i = 0; i < 4; i++)
        ((uint4*)dst)[i] = ((const uint4*)h)[i];
}

// ---------------- stage load: A[128] + B[128] rows x 64B ----------------
__device__ __forceinline__ void load_stage(const __half* __restrict__ ga0,
                                           const __half* __restrict__ gb0,
                                           int ks, int s, uint32_t sb, int tid) {
    uint32_t sA = sb + SM_A + s * ASTG;
    uint32_t sB = sb + SM_B + s * ASTG;
    const __half* ga = ga0 + ks * BK;
    const __half* gb = gb0 + ks * BK;
#pragma unroll
    for (int i = 0; i < 2; i++) {              // 512 16B-chunks / 256 thr = 2
        int q = tid + i * THREADS;
        int r = q >> 2, c = q & 3;
        CP_ASYNC16(sA + r * ROWB + c * 16, ga + (size_t)r * KTOT + c * 8);
    }
#pragma unroll
    for (int i = 0; i < 2; i++) {
        int q = tid + i * THREADS;
        int r = q >> 2, c = q & 3;
        CP_ASYNC16(sB + r * ROWB + c * 16, gb + (size_t)r * KTOT + c * 8);
    }
}

// ---------------- kernel ----------------
__global__ void __launch_bounds__(THREADS, 2)
fused_linear_gn_ht_kernel(const __half* __restrict__ xs,
                          const __half* __restrict__ ws,
                          const float* __restrict__ bias,
                          const float* __restrict__ gnw,
                          const float* __restrict__ gnb,
                          float* __restrict__ out) {
    extern __shared__ char smem[];
    uint32_t sb = smem_u32(smem);
    int tid = threadIdx.x;
    int wid = tid >> 5, lid = tid & 31;
    int wm = wid >> 1, wn = wid & 1;           // warp grid 4 (M) x 2 (N)
    int gid = lid >> 2, tid4 = lid & 3;
    int bn = blockIdx.x, bm = blockIdx.y;

    float* bias_s = (float*)(smem + SM_BIAS);
    float* gnw_s  = (float*)(smem + SM_GNW);
    float* gnb_s  = (float*)(smem + SM_GNB);
    if (tid < BN) {
        bias_s[tid] = bias[bn * BN + tid];
        gnw_s[tid]  = gnw[bn * BN + tid];
        gnb_s[tid]  = gnb[bn * BN + tid];
    }

    const __half* ga0 = xs + (size_t)bm * BM * KTOT;
    const __half* gb0 = ws + (size_t)bn * BN * KTOT;

#pragma unroll
    for (int p = 0; p < STAGES - 1; p++) {
        load_stage(ga0, gb0, p, p, sb, tid);
        CP_COMMIT();
    }

    float acc[2][8][4];
#pragma unroll
    for (int mi = 0; mi < 2; mi++)
#pragma unroll
        for (int ni = 0; ni < 8; ni++)
#pragma unroll
            for (int j = 0; j < 4; j++) acc[mi][ni][j] = 0.f;

    int rowA0 = wm * 32 + gid;
    int rowB0 = wn * 64 + gid;
    uint32_t fragOff = (uint32_t)tid4 * 16;     // t4 chunk within 64B row

    for (int k = 0; k < KSTEPS; k++) {
        int s = k & (STAGES - 1);
        CP_WAIT(STAGES - 2);
        __syncthreads();

        int lk = k + STAGES - 1;
        if (lk < KSTEPS) {
            load_stage(ga0, gb0, lk, (lk & (STAGES - 1)), sb, tid);
        }
        CP_COMMIT();

        uint32_t As = sb + SM_A + s * ASTG;
        uint32_t Bs = sb + SM_B + s * ASTG;

        // A fragments: [mi] rows r (lo) and r+8 (hi); each LDS.128 carries both k16 blks
        uint32_t alo[2][4], ahi[2][4], bfr[8][4];
#pragma unroll
        for (int mi = 0; mi < 2; mi++) {
            int r = rowA0 + mi * 16;
            LDS128(alo[mi][0], alo[mi][1], alo[mi][2], alo[mi][3],
                   As + r * ROWB + fragOff);
            LDS128(ahi[mi][0], ahi[mi][1], ahi[mi][2], ahi[mi][3],
                   As + (r + 8) * ROWB + fragOff);
        }
#pragma unroll
        for (int ni = 0; ni < 8; ni++) {
            LDS128(bfr[ni][0], bfr[ni][1], bfr[ni][2], bfr[ni][3],
                   Bs + (rowB0 + ni * 8) * ROWB + fragOff);
        }

#pragma unroll
        for (int blk = 0; blk < 2; blk++) {
#pragma unroll
            for (int mi = 0; mi < 2; mi++)
#pragma unroll
                for (int ni = 0; ni < 8; ni++)
                    mma_f16(acc[mi][ni],
                            alo[mi][blk * 2 + 0], ahi[mi][blk * 2 + 0],
                            alo[mi][blk * 2 + 1], ahi[mi][blk * 2 + 1],
                            bfr[ni][blk * 2 + 0], bfr[ni][blk * 2 + 1]);
        }
    }

    // ---------------- fused epilogue: bias + GroupNorm(64) + hardtanh ----------------
    int gcol = wn * 64;
    size_t gout = (size_t)bn * BN + gcol;

#pragma unroll
    for (int mi = 0; mi < 2; mi++) {
#pragma unroll
        for (int half = 0; half < 2; half++) {
            int row_l = wm * 32 + mi * 16 + half * 8 + gid;
            float sum = 0.f, ssq = 0.f;
            float v[8][2];
#pragma unroll
            for (int ni = 0; ni < 8; ni++) {
                int c = ni * 8 + 2 * tid4;
                float v0 = acc[mi][ni][half * 2 + 0] + bias_s[gcol + c + 0];
                float v1 = acc[mi][ni][half * 2 + 1] + bias_s[gcol + c + 1];
                v[ni][0] = v0; v[ni][1] = v1;
                sum += v0 + v1;
                ssq += v0 * v0 + v1 * v1;
            }
            sum += __shfl_xor_sync(0xffffffffu, sum, 1);
            ssq += __shfl_xor_sync(0xffffffffu, ssq, 1);
            sum += __shfl_xor_sync(0xffffffffu, sum, 2);
            ssq += __shfl_xor_sync(0xffffffffu, ssq, 2);

            float mean = sum * (1.f / 64.f);
            float var  = ssq * (1.f / 64.f) - mean * mean;
            float inv  = rsqrtf(var + 1e-5f);

            size_t orow = (size_t)(bm * BM + row_l) * NTOT + gout;
#pragma unroll
            for (int ni = 0; ni < 8; ni++) {
                int c = ni * 8 + 2 * tid4;
                float2 o;
                o.x = fminf(fmaxf((v[ni][0] - mean) * inv * gnw_s[gcol + c + 0]
                                  + gnb_s[gcol + c + 0], -1.f), 1.f);
                o.y = fminf(fmaxf((v[ni][1] - mean) * inv * gnw_s[gcol + c + 1]
                                  + gnb_s[gcol + c + 1], -1.f), 1.f);
                *(float2*)(out + orow + c) = o;
            }
        }
    }
}

// ---------------- launch ----------------
extern "C" void kernel_launch(void* const* d_in, const int* in_sizes, int n_in,
                              void* d_out, int out_size) {
    const float* x    = (const float*)d_in[0];
    const float* w    = (const float*)d_in[1];
    const float* bias = (const float*)d_in[2];
    const float* gnw  = (const float*)d_in[3];
    const float* gnb  = (const float*)d_in[4];
    float* out = (float*)d_out;

    static bool attr_done = false;
    if (!attr_done) {
        cudaFuncSetAttribute(fused_linear_gn_ht_kernel,
                             cudaFuncAttributeMaxDynamicSharedMemorySize, SMEM_TOTAL);
        attr_done = true;
    }

    __half* xs; __half* ws;
    cudaGetSymbolAddress((void**)&xs, g_xsh);
    cudaGetSymbolAddress((void**)&ws, g_wsh);

    int nunit = ((MTOT + NTOT) * KTOT) / 32;    // 393216
    prepass_kernel<<<(nunit + 255) / 256, 256>>>(x, w, nunit);

    dim3 grid(NTOT / BN, MTOT / BM);   // (16, 32) = 512 CTAs
    fused_linear_gn_ht_kernel<<<grid, THREADS, SMEM_TOTAL>>>(xs, ws, bias, gnw, gnb, out);
}

// round 8
// speedup vs baseline: 1.9851x; 1.0836x over previous
#include <cuda_runtime.h>
#include <cuda_fp16.h>
#include <cstdint>

// ---------------- problem constants ----------------
#define MTOT 4096
#define NTOT 2048
#define KTOT 2048
#define BM   128
#define BN   128
#define BK   32
#define STAGES 4
#define KSTEPS (KTOT / BK)          // 64
#define THREADS 256

// fp16 smem stage row: 32 halves = 64B, permuted so each thread's fragment is LDS.128
#define ROWB 64
#define ASTG (BM * ROWB)            // 8192 bytes per stage (A or B)

// ---------------- smem layout (bytes) ----------------
#define SM_BIAS 0
#define SM_GNW  512
#define SM_GNB  1024
#define SM_A    2048
#define SM_B    (SM_A + STAGES * ASTG)            // 34816
#define SMEM_TOTAL (SM_B + STAGES * ASTG)         // 67584 (66KB) -> 2 CTA/SM

// ---------------- fp16, fragment-permuted scratch ----------------
__device__ __half g_xsh[(size_t)MTOT * KTOT];   // 16 MB
__device__ __half g_wsh[(size_t)NTOT * KTOT];   //  8 MB

// ---------------- PTX helpers ----------------
__device__ __forceinline__ uint32_t smem_u32(const void* p) {
    uint32_t a;
    asm("{ .reg .u64 t; cvta.to.shared.u64 t, %1; cvt.u32.u64 %0, t; }"
        : "=r"(a) : "l"(p));
    return a;
}

#define CP_ASYNC16(s, g) \
    asm volatile("cp.async.cg.shared.global [%0], [%1], 16;" :: "r"(s), "l"(g) : "memory")
#define CP_COMMIT() asm volatile("cp.async.commit_group;" ::: "memory")
#define CP_WAIT(n)  asm volatile("cp.async.wait_group %0;" :: "n"(n) : "memory")

#define LDS128(r0, r1, r2, r3, addr) \
    asm volatile("ld.shared.v4.u32 {%0, %1, %2, %3}, [%4];" \
                 : "=r"(r0), "=r"(r1), "=r"(r2), "=r"(r3) : "r"(addr))

__device__ __forceinline__ void mma_f16(float* c, uint32_t a0, uint32_t a1,
                                        uint32_t a2, uint32_t a3,
                                        uint32_t b0, uint32_t b1) {
    asm volatile(
        "mma.sync.aligned.m16n8k16.row.col.f32.f16.f16.f32 "
        "{%0,%1,%2,%3}, {%4,%5,%6,%7}, {%8,%9}, {%0,%1,%2,%3};"
        : "+f"(c[0]), "+f"(c[1]), "+f"(c[2]), "+f"(c[3])
        : "r"(a0), "r"(a1), "r"(a2), "r"(a3), "r"(b0), "r"(b1));
}

// ---------------- prepass: fp32 -> fp16 + fragment permutation ----------------
__global__ void __launch_bounds__(256)
prepass_kernel(const float* __restrict__ x, const float* __restrict__ w, int nunit) {
    int u = blockIdx.x * 256 + threadIdx.x;
    if (u >= nunit) return;
    int row = u >> 6;                  // 64 units of 32 cols per 2048-col row
    int uc  = u & 63;
    const float* src;
    __half* dst;
    if (row < MTOT) {
        src = x + (size_t)row * KTOT + uc * 32;
        dst = g_xsh + (size_t)row * KTOT + uc * 32;
    } else {
        src = w + (size_t)(row - MTOT) * KTOT + uc * 32;
        dst = g_wsh + (size_t)(row - MTOT) * KTOT + uc * 32;
    }
    float v[32];
#pragma unroll
    for (int i = 0; i < 8; i++) {
        float4 f = ((const float4*)src)[i];
        v[i * 4 + 0] = f.x; v[i * 4 + 1] = f.y; v[i * 4 + 2] = f.z; v[i * 4 + 3] = f.w;
    }
    __half h[32];
#pragma unroll
    for (int t4 = 0; t4 < 4; t4++) {
#pragma unroll
        for (int blk = 0; blk < 2; blk++) {
            int o = t4 * 8 + blk * 4;
            int c = blk * 16 + 2 * t4;
            h[o + 0] = __float2half_rn(v[c + 0]);
            h[o + 1] = __float2half_rn(v[c + 1]);
            h[o + 2] = __float2half_rn(v[c + 8]);
            h[o + 3] = __float2half_rn(v[c + 9]);
        }
    }
#pragma unroll
    for (int i = 0; i < 4; i++)
        ((uint4*)dst)[i] = ((const uint4*)h)[i];
}

// ---------------- kernel ----------------
__global__ void __launch_bounds__(THREADS, 2)
fused_linear_gn_ht_kernel(const __half* __restrict__ xs,
                          const __half* __restrict__ ws,
                          const float* __restrict__ bias,
                          const float* __restrict__ gnw,
                          const float* __restrict__ gnb,
                          float* __restrict__ out) {
    extern __shared__ char smem[];
    uint32_t sb = smem_u32(smem);
    int tid = threadIdx.x;
    int wid = tid >> 5, lid = tid & 31;
    int wm = wid >> 1, wn = wid & 1;           // warp grid 4 (M) x 2 (N)
    int gid = lid >> 2, tid4 = lid & 3;
    int bn = blockIdx.x, bm = blockIdx.y;

    float* bias_s = (float*)(smem + SM_BIAS);
    float* gnw_s  = (float*)(smem + SM_GNW);
    float* gnb_s  = (float*)(smem + SM_GNB);
    if (tid < BN) {
        bias_s[tid] = bias[bn * BN + tid];
        gnw_s[tid]  = gnw[bn * BN + tid];
        gnb_s[tid]  = gnb[bn * BN + tid];
    }

    const __half* ga0 = xs + (size_t)bm * BM * KTOT;
    const __half* gb0 = ws + (size_t)bn * BN * KTOT;

    // per-thread cp.async geometry: chunk q in [0,512): r = q>>2, c = q&3
    int rA0 = (tid) >> 2,            cA0 = tid & 3;
    int rA1 = (tid + THREADS) >> 2,  cA1 = cA0;          // same c, row +64
    uint32_t aRC0 = (uint32_t)(rA0 * ROWB + cA0 * 16);   // smem offset within stage
    uint32_t aRC1 = (uint32_t)(rA1 * ROWB + cA1 * 16);
    const __half* aP0 = ga0 + (size_t)rA0 * KTOT + cA0 * 8;
    const __half* aP1 = ga0 + (size_t)rA1 * KTOT + cA1 * 8;
    const __half* bP0 = gb0 + (size_t)rA0 * KTOT + cA0 * 8;
    const __half* bP1 = gb0 + (size_t)rA1 * KTOT + cA1 * 8;
    uint32_t aSm0 = sb + SM_A + aRC0, aSm1 = sb + SM_A + aRC1;
    uint32_t bSm0 = sb + SM_B + aRC0, bSm1 = sb + SM_B + aRC1;

    // prologue: stages 0..2
#pragma unroll
    for (int p = 0; p < STAGES - 1; p++) {
        CP_ASYNC16(aSm0 + p * ASTG, aP0 + p * BK);
        CP_ASYNC16(aSm1 + p * ASTG, aP1 + p * BK);
        CP_ASYNC16(bSm0 + p * ASTG, bP0 + p * BK);
        CP_ASYNC16(bSm1 + p * ASTG, bP1 + p * BK);
        CP_COMMIT();
    }
    aP0 += (STAGES - 1) * BK; aP1 += (STAGES - 1) * BK;
    bP0 += (STAGES - 1) * BK; bP1 += (STAGES - 1) * BK;

    float acc[2][8][4];
#pragma unroll
    for (int mi = 0; mi < 2; mi++)
#pragma unroll
        for (int ni = 0; ni < 8; ni++)
#pragma unroll
            for (int j = 0; j < 4; j++) acc[mi][ni][j] = 0.f;

    // fragment LDS base addresses (stage-invariant; stage enters as immediate)
    uint32_t fragOff = (uint32_t)tid4 * 16;
    int rowA0 = wm * 32 + gid;
    int rowB0 = wn * 64 + gid;
    uint32_t aAd[4], bAd[8];
#pragma unroll
    for (int j = 0; j < 4; j++) aAd[j] = sb + (rowA0 + j * 8) * ROWB + fragOff;
#pragma unroll
    for (int ni = 0; ni < 8; ni++) bAd[ni] = sb + (rowB0 + ni * 8) * ROWB + fragOff;

#define KITER(S)                                                                 \
    do {                                                                         \
        CP_WAIT(STAGES - 2);                                                     \
        __syncthreads();                                                         \
        if (k0 + (S) + STAGES - 1 < KSTEPS) {                                    \
            constexpr int PS = ((S) + STAGES - 1) & (STAGES - 1);                \
            CP_ASYNC16(aSm0 + PS * ASTG, aP0);                                   \
            CP_ASYNC16(aSm1 + PS * ASTG, aP1);                                   \
            CP_ASYNC16(bSm0 + PS * ASTG, bP0);                                   \
            CP_ASYNC16(bSm1 + PS * ASTG, bP1);                                   \
            aP0 += BK; aP1 += BK; bP0 += BK; bP1 += BK;                          \
        }                                                                        \
        CP_COMMIT();                                                             \
        uint32_t alo[2][4], ahi[2][4], bfr[8][4];                                \
        _Pragma("unroll")                                                        \
        for (int mi = 0; mi < 2; mi++) {                                         \
            LDS128(alo[mi][0], alo[mi][1], alo[mi][2], alo[mi][3],               \
                   aAd[2 * mi] + (SM_A + (S) * ASTG));                           \
            LDS128(ahi[mi][0], ahi[mi][1], ahi[mi][2], ahi[mi][3],               \
                   aAd[2 * mi + 1] + (SM_A + (S) * ASTG));                       \
        }                                                                        \
        _Pragma("unroll")                                                        \
        for (int ni = 0; ni < 8; ni++) {                                         \
            LDS128(bfr[ni][0], bfr[ni][1], bfr[ni][2], bfr[ni][3],               \
                   bAd[ni] + (SM_B + (S) * ASTG));                               \
        }                                                                        \
        _Pragma("unroll")                                                        \
        for (int blk = 0; blk < 2; blk++)                                        \
            _Pragma("unroll")                                                    \
            for (int mi = 0; mi < 2; mi++)                                       \
                _Pragma("unroll")                                                \
                for (int ni = 0; ni < 8; ni++)                                   \
                    mma_f16(acc[mi][ni],                                         \
                            alo[mi][blk * 2 + 0], ahi[mi][blk * 2 + 0],          \
                            alo[mi][blk * 2 + 1], ahi[mi][blk * 2 + 1],          \
                            bfr[ni][blk * 2 + 0], bfr[ni][blk * 2 + 1]);         \
    } while (0)

    for (int k0 = 0; k0 < KSTEPS; k0 += STAGES) {
        KITER(0);
        KITER(1);
        KITER(2);
        KITER(3);
    }
#undef KITER

    // ---------------- fused epilogue: bias + GroupNorm(64) + hardtanh ----------------
    int gcol = wn * 64;
    size_t gout = (size_t)bn * BN + gcol;

#pragma unroll
    for (int mi = 0; mi < 2; mi++) {
#pragma unroll
        for (int half = 0; half < 2; half++) {
            int row_l = wm * 32 + mi * 16 + half * 8 + gid;
            float sum = 0.f, ssq = 0.f;
            float v[8][2];
#pragma unroll
            for (int ni = 0; ni < 8; ni++) {
                int c = ni * 8 + 2 * tid4;
                float v0 = acc[mi][ni][half * 2 + 0] + bias_s[gcol + c + 0];
                float v1 = acc[mi][ni][half * 2 + 1] + bias_s[gcol + c + 1];
                v[ni][0] = v0; v[ni][1] = v1;
                sum += v0 + v1;
                ssq += v0 * v0 + v1 * v1;
            }
            sum += __shfl_xor_sync(0xffffffffu, sum, 1);
            ssq += __shfl_xor_sync(0xffffffffu, ssq, 1);
            sum += __shfl_xor_sync(0xffffffffu, sum, 2);
            ssq += __shfl_xor_sync(0xffffffffu, ssq, 2);

            float mean = sum * (1.f / 64.f);
            float var  = ssq * (1.f / 64.f) - mean * mean;
            float inv  = rsqrtf(var + 1e-5f);

            size_t orow = (size_t)(bm * BM + row_l) * NTOT + gout;
#pragma unroll
            for (int ni = 0; ni < 8; ni++) {
                int c = ni * 8 + 2 * tid4;
                float2 o;
                o.x = fminf(fmaxf((v[ni][0] - mean) * inv * gnw_s[gcol + c + 0]
                                  + gnb_s[gcol + c + 0], -1.f), 1.f);
                o.y = fminf(fmaxf((v[ni][1] - mean) * inv * gnw_s[gcol + c + 1]
                                  + gnb_s[gcol + c + 1], -1.f), 1.f);
                *(float2*)(out + orow + c) = o;
            }
        }
    }
}

// ---------------- launch ----------------
extern "C" void kernel_launch(void* const* d_in, const int* in_sizes, int n_in,
                              void* d_out, int out_size) {
    const float* x    = (const float*)d_in[0];
    const float* w    = (const float*)d_in[1];
    const float* bias = (const float*)d_in[2];
    const float* gnw  = (const float*)d_in[3];
    const float* gnb  = (const float*)d_in[4];
    float* out = (float*)d_out;

    static bool attr_done = false;
    if (!attr_done) {
        cudaFuncSetAttribute(fused_linear_gn_ht_kernel,
                             cudaFuncAttributeMaxDynamicSharedMemorySize, SMEM_TOTAL);
        attr_done = true;
    }

    __half* xs; __half* ws;
    cudaGetSymbolAddress((void**)&xs, g_xsh);
    cudaGetSymbolAddress((void**)&ws, g_wsh);

    int nunit = ((MTOT + NTOT) * KTOT) / 32;    // 393216
    prepass_kernel<<<(nunit + 255) / 256, 256>>>(x, w, nunit);

    dim3 grid(NTOT / BN, MTOT / BM);   // (16, 32) = 512 CTAs
    fused_linear_gn_ht_kernel<<<grid, THREADS, SMEM_TOTAL>>>(xs, ws, bias, gnw, gnb, out);
}

// round 10
// speedup vs baseline: 2.0983x; 1.0571x over previous
#include <cuda_runtime.h>
#include <cuda_fp16.h>
#include <cstdint>

// ---------------- problem constants ----------------
#define MTOT 4096
#define NTOT 2048
#define KTOT 2048
#define BM   128
#define BN   128
#define BK   32
#define STAGES 4
#define KSTEPS (KTOT / BK)          // 64
#define THREADS 256

// fp16 smem stage row: 32 halves = 64B, permuted so each thread's fragment is LDS.128
#define ROWB 64
#define ASTG (BM * ROWB)            // 8192 bytes per stage (A or B)

// ---------------- smem layout (bytes) ----------------
#define SM_BIAS 0
#define SM_GNW  512
#define SM_GNB  1024
#define SM_A    2048
#define SM_B    (SM_A + STAGES * ASTG)            // 34816
#define SMEM_TOTAL (SM_B + STAGES * ASTG)         // 67584 (66KB) -> 2 CTA/SM
#define B_OFF (SM_B - SM_A)                       // 32768

// ---------------- fp16, fragment-permuted scratch ----------------
__device__ __half g_xsh[(size_t)MTOT * KTOT];   // 16 MB
__device__ __half g_wsh[(size_t)NTOT * KTOT];   //  8 MB

// ---------------- PTX helpers ----------------
__device__ __forceinline__ uint32_t smem_u32(const void* p) {
    uint32_t a;
    asm("{ .reg .u64 t; cvta.to.shared.u64 t, %1; cvt.u32.u64 %0, t; }"
        : "=r"(a) : "l"(p));
    return a;
}

// cp.async with compile-time byte offsets on BOTH addresses
#define CP_A16I(smreg, gptr, smimm, gimm) \
    asm volatile("cp.async.cg.shared.global [%0+%2], [%1+%3], 16;" \
                 :: "r"(smreg), "l"(gptr), "n"(smimm), "n"(gimm) : "memory")
#define CP_COMMIT() asm volatile("cp.async.commit_group;" ::: "memory")
#define CP_WAIT(n)  asm volatile("cp.async.wait_group %0;" :: "n"(n) : "memory")

// LDS.128 with compile-time byte offset (imm MUST be a literal-constant expression)
#define LDS128I(r0, r1, r2, r3, base, imm) \
    asm volatile("ld.shared.v4.u32 {%0, %1, %2, %3}, [%4+%5];" \
                 : "=r"(r0), "=r"(r1), "=r"(r2), "=r"(r3) : "r"(base), "n"(imm))

__device__ __forceinline__ void mma_f16(float* c, uint32_t a0, uint32_t a1,
                                        uint32_t a2, uint32_t a3,
                                        uint32_t b0, uint32_t b1) {
    asm volatile(
        "mma.sync.aligned.m16n8k16.row.col.f32.f16.f16.f32 "
        "{%0,%1,%2,%3}, {%4,%5,%6,%7}, {%8,%9}, {%0,%1,%2,%3};"
        : "+f"(c[0]), "+f"(c[1]), "+f"(c[2]), "+f"(c[3])
        : "r"(a0), "r"(a1), "r"(a2), "r"(a3), "r"(b0), "r"(b1));
}

// ---------------- prepass: fp32 -> fp16 + fragment permutation ----------------
__global__ void __launch_bounds__(256)
prepass_kernel(const float* __restrict__ x, const float* __restrict__ w, int nunit) {
    int u = blockIdx.x * 256 + threadIdx.x;
    if (u >= nunit) return;
    int row = u >> 6;
    int uc  = u & 63;
    const float* src;
    __half* dst;
    if (row < MTOT) {
        src = x + (size_t)row * KTOT + uc * 32;
        dst = g_xsh + (size_t)row * KTOT + uc * 32;
    } else {
        src = w + (size_t)(row - MTOT) * KTOT + uc * 32;
        dst = g_wsh + (size_t)(row - MTOT) * KTOT + uc * 32;
    }
    float v[32];
#pragma unroll
    for (int i = 0; i < 8; i++) {
        float4 f = ((const float4*)src)[i];
        v[i * 4 + 0] = f.x; v[i * 4 + 1] = f.y; v[i * 4 + 2] = f.z; v[i * 4 + 3] = f.w;
    }
    __half h[32];
#pragma unroll
    for (int t4 = 0; t4 < 4; t4++) {
#pragma unroll
        for (int blk = 0; blk < 2; blk++) {
            int o = t4 * 8 + blk * 4;
            int c = blk * 16 + 2 * t4;
            h[o + 0] = __float2half_rn(v[c + 0]);
            h[o + 1] = __float2half_rn(v[c + 1]);
            h[o + 2] = __float2half_rn(v[c + 8]);
            h[o + 3] = __float2half_rn(v[c + 9]);
        }
    }
#pragma unroll
    for (int i = 0; i < 4; i++)
        ((uint4*)dst)[i] = ((const uint4*)h)[i];
}

// ---------------- kernel ----------------
__global__ void __launch_bounds__(THREADS, 2)
fused_linear_gn_ht_kernel(const __half* __restrict__ xs,
                          const __half* __restrict__ ws,
                          const float* __restrict__ bias,
                          const float* __restrict__ gnw,
                          const float* __restrict__ gnb,
                          float* __restrict__ out) {
    extern __shared__ char smem[];
    uint32_t sb = smem_u32(smem);
    int tid = threadIdx.x;
    int wid = tid >> 5, lid = tid & 31;
    int wm = wid >> 1, wn = wid & 1;           // warp grid 4 (M) x 2 (N)
    int gid = lid >> 2, tid4 = lid & 3;
    int bn = blockIdx.x, bm = blockIdx.y;

    float* bias_s = (float*)(smem + SM_BIAS);
    float* gnw_s  = (float*)(smem + SM_GNW);
    float* gnb_s  = (float*)(smem + SM_GNB);
    if (tid < BN) {
        bias_s[tid] = bias[bn * BN + tid];
        gnw_s[tid]  = gnw[bn * BN + tid];
        gnb_s[tid]  = gnb[bn * BN + tid];
    }

    // ---- minimal address state: 1 smem-dst reg, 2 global ptr regs, 2 frag base regs
    int rA = tid >> 2, cA = tid & 3;           // cp.async geometry, chunk q=tid
    uint32_t cpSm = sb + SM_A + (uint32_t)(rA * ROWB + cA * 16);
    const __half* aPtr = xs + (size_t)bm * BM * KTOT + (size_t)rA * KTOT + cA * 8;
    const __half* bPtr = ws + (size_t)bn * BN * KTOT + (size_t)rA * KTOT + cA * 8;
    // second chunk (row +64): global +64*KTOT*2 = 262144 bytes, smem +64*ROWB = 4096
#define GCH 262144
#define SCH 4096

    // prologue: stages 0..2
#define PRO(p) do {                                                   \
        CP_A16I(cpSm, aPtr, (p) * ASTG,           (p) * 64);          \
        CP_A16I(cpSm, aPtr, (p) * ASTG + SCH,     (p) * 64 + GCH);    \
        CP_A16I(cpSm, bPtr, (p) * ASTG + B_OFF,       (p) * 64);      \
        CP_A16I(cpSm, bPtr, (p) * ASTG + B_OFF + SCH, (p) * 64 + GCH);\
        CP_COMMIT();                                                  \
    } while (0)
    PRO(0); PRO(1); PRO(2);
#undef PRO
    aPtr += (STAGES - 1) * BK;
    bPtr += (STAGES - 1) * BK;

    float acc[2][8][4];
#pragma unroll
    for (int mi = 0; mi < 2; mi++)
#pragma unroll
        for (int ni = 0; ni < 8; ni++)
#pragma unroll
            for (int j = 0; j < 4; j++) acc[mi][ni][j] = 0.f;

    // fragment base addresses (2 registers; everything else immediate)
    uint32_t aBase = sb + SM_A + (uint32_t)((wm * 32 + gid) * ROWB + tid4 * 16);
    uint32_t bBase = sb + SM_B + (uint32_t)((wn * 64 + gid) * ROWB + tid4 * 16);

    // ---- fully expanded fragment loads (literal immediates only) ----
#define LD_FRAGS(S)                                                              \
        LDS128I(alo[0][0], alo[0][1], alo[0][2], alo[0][3], aBase,               \
                (S) * ASTG + 0 * 512);                                           \
        LDS128I(ahi[0][0], ahi[0][1], ahi[0][2], ahi[0][3], aBase,               \
                (S) * ASTG + 1 * 512);                                           \
        LDS128I(alo[1][0], alo[1][1], alo[1][2], alo[1][3], aBase,               \
                (S) * ASTG + 2 * 512);                                           \
        LDS128I(ahi[1][0], ahi[1][1], ahi[1][2], ahi[1][3], aBase,               \
                (S) * ASTG + 3 * 512);                                           \
        LDS128I(bfr[0][0], bfr[0][1], bfr[0][2], bfr[0][3], bBase,               \
                (S) * ASTG + 0 * 512);                                           \
        LDS128I(bfr[1][0], bfr[1][1], bfr[1][2], bfr[1][3], bBase,               \
                (S) * ASTG + 1 * 512);                                           \
        LDS128I(bfr[2][0], bfr[2][1], bfr[2][2], bfr[2][3], bBase,               \
                (S) * ASTG + 2 * 512);                                           \
        LDS128I(bfr[3][0], bfr[3][1], bfr[3][2], bfr[3][3], bBase,               \
                (S) * ASTG + 3 * 512);                                           \
        LDS128I(bfr[4][0], bfr[4][1], bfr[4][2], bfr[4][3], bBase,               \
                (S) * ASTG + 4 * 512);                                           \
        LDS128I(bfr[5][0], bfr[5][1], bfr[5][2], bfr[5][3], bBase,               \
                (S) * ASTG + 5 * 512);                                           \
        LDS128I(bfr[6][0], bfr[6][1], bfr[6][2], bfr[6][3], bBase,               \
                (S) * ASTG + 6 * 512);                                           \
        LDS128I(bfr[7][0], bfr[7][1], bfr[7][2], bfr[7][3], bBase,               \
                (S) * ASTG + 7 * 512);

#define KITER(S)                                                                 \
    do {                                                                         \
        CP_WAIT(STAGES - 2);                                                     \
        __syncthreads();                                                         \
        if (k0 + (S) + STAGES - 1 < KSTEPS) {                                    \
            constexpr int PS = ((S) + STAGES - 1) & (STAGES - 1);                \
            CP_A16I(cpSm, aPtr, PS * ASTG,           (S) * 64);                  \
            CP_A16I(cpSm, aPtr, PS * ASTG + SCH,     (S) * 64 + GCH);            \
            CP_A16I(cpSm, bPtr, PS * ASTG + B_OFF,       (S) * 64);              \
            CP_A16I(cpSm, bPtr, PS * ASTG + B_OFF + SCH, (S) * 64 + GCH);        \
        }                                                                        \
        CP_COMMIT();                                                             \
        uint32_t alo[2][4], ahi[2][4], bfr[8][4];                                \
        LD_FRAGS(S)                                                              \
        _Pragma("unroll")                                                        \
        for (int blk = 0; blk < 2; blk++)                                        \
            _Pragma("unroll")                                                    \
            for (int mi = 0; mi < 2; mi++)                                       \
                _Pragma("unroll")                                                \
                for (int ni = 0; ni < 8; ni++)                                   \
                    mma_f16(acc[mi][ni],                                         \
                            alo[mi][blk * 2 + 0], ahi[mi][blk * 2 + 0],          \
                            alo[mi][blk * 2 + 1], ahi[mi][blk * 2 + 1],          \
                            bfr[ni][blk * 2 + 0], bfr[ni][blk * 2 + 1]);         \
    } while (0)

    for (int k0 = 0; k0 < KSTEPS; k0 += STAGES) {
        KITER(0);
        KITER(1);
        KITER(2);
        KITER(3);
        aPtr += STAGES * BK;          // one bump per 4 k-steps
        bPtr += STAGES * BK;
    }
#undef KITER
#undef LD_FRAGS

    // ---------------- fused epilogue: bias + GroupNorm(64) + hardtanh ----------------
    int gcol = wn * 64;
    size_t gout = (size_t)bn * BN + gcol;

#pragma unroll
    for (int mi = 0; mi < 2; mi++) {
#pragma unroll
        for (int half = 0; half < 2; half++) {
            int row_l = wm * 32 + mi * 16 + half * 8 + gid;
            float sum = 0.f, ssq = 0.f;
            float v[8][2];
#pragma unroll
            for (int ni = 0; ni < 8; ni++) {
                int c = ni * 8 + 2 * tid4;
                float v0 = acc[mi][ni][half * 2 + 0] + bias_s[gcol + c + 0];
                float v1 = acc[mi][ni][half * 2 + 1] + bias_s[gcol + c + 1];
                v[ni][0] = v0; v[ni][1] = v1;
                sum += v0 + v1;
                ssq += v0 * v0 + v1 * v1;
            }
            sum += __shfl_xor_sync(0xffffffffu, sum, 1);
            ssq += __shfl_xor_sync(0xffffffffu, ssq, 1);
            sum += __shfl_xor_sync(0xffffffffu, sum, 2);
            ssq += __shfl_xor_sync(0xffffffffu, ssq, 2);

            float mean = sum * (1.f / 64.f);
            float var  = ssq * (1.f / 64.f) - mean * mean;
            float inv  = rsqrtf(var + 1e-5f);

            size_t orow = (size_t)(bm * BM + row_l) * NTOT + gout;
#pragma unroll
            for (int ni = 0; ni < 8; ni++) {
                int c = ni * 8 + 2 * tid4;
                float2 o;
                o.x = fminf(fmaxf((v[ni][0] - mean) * inv * gnw_s[gcol + c + 0]
                                  + gnb_s[gcol + c + 0], -1.f), 1.f);
                o.y = fminf(fmaxf((v[ni][1] - mean) * inv * gnw_s[gcol + c + 1]
                                  + gnb_s[gcol + c + 1], -1.f), 1.f);
                *(float2*)(out + orow + c) = o;
            }
        }
    }
}

// ---------------- launch ----------------
extern "C" void kernel_launch(void* const* d_in, const int* in_sizes, int n_in,
                              void* d_out, int out_size) {
    const float* x    = (const float*)d_in[0];
    const float* w    = (const float*)d_in[1];
    const float* bias = (const float*)d_in[2];
    const float* gnw  = (const float*)d_in[3];
    const float* gnb  = (const float*)d_in[4];
    float* out = (float*)d_out;

    static bool attr_done = false;
    if (!attr_done) {
        cudaFuncSetAttribute(fused_linear_gn_ht_kernel,
                             cudaFuncAttributeMaxDynamicSharedMemorySize, SMEM_TOTAL);
        attr_done = true;
    }

    __half* xs; __half* ws;
    cudaGetSymbolAddress((void**)&xs, g_xsh);
    cudaGetSymbolAddress((void**)&ws, g_wsh);

    int nunit = ((MTOT + NTOT) * KTOT) / 32;    // 393216
    prepass_kernel<<<(nunit + 255) / 256, 256>>>(x, w, nunit);

    dim3 grid(NTOT / BN, MTOT / BM);   // (16, 32) = 512 CTAs
    fused_linear_gn_ht_kernel<<<grid, THREADS, SMEM_TOTAL>>>(xs, ws, bias, gnw, gnb, out);
}